// round 3
// baseline (speedup 1.0000x reference)
#include <cuda_runtime.h>

#define BATCH   4
#define CIN     256
#define HID     128
#define NHEADS  4
#define DHEAD   32
#define NTOK    4096
#define QKV_ROWS 384

// Scratch (no allocations allowed in kernel_launch)
__device__ float g_qkv[BATCH * QKV_ROWS * NTOK];   // [b][384][4096]
__device__ float g_att[BATCH * HID * NTOK];        // [b][128][4096]

// ---------------------------------------------------------------------------
// Kernel 1: qkv = W_qkv (384x256) @ x[b] (256x4096)   -> g_qkv
// 64x64 tile, 256 threads, 4x4 register blocking, K-step 16.
// ---------------------------------------------------------------------------
__global__ __launch_bounds__(256) void qkv_gemm(const float* __restrict__ X,
                                                const float* __restrict__ W) {
    __shared__ float Ws[16][64];
    __shared__ float Xs[16][64];

    const int b  = blockIdx.z;
    const int M0 = blockIdx.y * 64;
    const int N0 = blockIdx.x * 64;
    const int tid = threadIdx.x;
    const int tx = tid & 15, ty = tid >> 4;

    const float* Xb = X + (size_t)b * CIN * NTOK;

    const int wm = tid >> 2,  wk = (tid & 3) * 4;   // W load mapping
    const int xk = tid >> 4,  xn = (tid & 15) * 4;  // X load mapping

    float acc[4][4] = {};

    for (int kk = 0; kk < CIN; kk += 16) {
        float4 w4 = *(const float4*)&W[(size_t)(M0 + wm) * CIN + kk + wk];
        Ws[wk + 0][wm] = w4.x; Ws[wk + 1][wm] = w4.y;
        Ws[wk + 2][wm] = w4.z; Ws[wk + 3][wm] = w4.w;
        *(float4*)&Xs[xk][xn] =
            *(const float4*)&Xb[(size_t)(kk + xk) * NTOK + N0 + xn];
        __syncthreads();
#pragma unroll
        for (int k = 0; k < 16; ++k) {
            float4 a4 = *(float4*)&Ws[k][ty * 4];
            float4 b4 = *(float4*)&Xs[k][tx * 4];
            float av[4] = {a4.x, a4.y, a4.z, a4.w};
            float bv[4] = {b4.x, b4.y, b4.z, b4.w};
#pragma unroll
            for (int a = 0; a < 4; ++a)
#pragma unroll
                for (int c = 0; c < 4; ++c)
                    acc[a][c] = fmaf(av[a], bv[c], acc[a][c]);
        }
        __syncthreads();
    }

    float* Cb = g_qkv + (size_t)b * QKV_ROWS * NTOK;
#pragma unroll
    for (int a = 0; a < 4; ++a) {
        float4 o = make_float4(acc[a][0], acc[a][1], acc[a][2], acc[a][3]);
        *(float4*)&Cb[(size_t)(M0 + ty * 4 + a) * NTOK + N0 + tx * 4] = o;
    }
}

// ---------------------------------------------------------------------------
// Kernel 2: flash attention per (b,h).  Q,K,V stored d-major [32][4096].
// Block: 64 queries; loop over 64-key tiles with online softmax.
// 256 threads = 16x16; each thread owns 4 S-rows x 4 S-cols, O = 4 rows x 2 d.
// ---------------------------------------------------------------------------
__global__ __launch_bounds__(256) void attn_kernel() {
    __shared__ float q_s[DHEAD][64];     // [d][i]
    __shared__ float k_s[DHEAD][64];     // [d][j]
    __shared__ float vT[64][DHEAD + 2];  // [j][d], pad 2 => stride 34 (aligned f2)
    __shared__ float P_s[64][64];        // [i][j]

    const int bh = blockIdx.y;           // 0..15
    const int b = bh >> 2, h = bh & 3;
    const int q0 = blockIdx.x * 64;
    const int tid = threadIdx.x;
    const int tx = tid & 15, ty = tid >> 4;
    const int d0 = tx * 2;

    const float* Qp = g_qkv + ((size_t)b * QKV_ROWS + h * DHEAD) * NTOK;
    const float* Kp = g_qkv + ((size_t)b * QKV_ROWS + HID + h * DHEAD) * NTOK;
    const float* Vp = g_qkv + ((size_t)b * QKV_ROWS + 2 * HID + h * DHEAD) * NTOK;

#pragma unroll
    for (int r = 0; r < 8; ++r) {
        int idx = tid + r * 256;
        int d = idx >> 6, i = idx & 63;
        q_s[d][i] = Qp[(size_t)d * NTOK + q0 + i];
    }

    const float scale = 0.17677669529663689f;  // 32^-0.5
    float m_i[4], l_i[4], O[4][2];
#pragma unroll
    for (int a = 0; a < 4; ++a) {
        m_i[a] = -1e30f; l_i[a] = 0.f; O[a][0] = 0.f; O[a][1] = 0.f;
    }

    for (int jt = 0; jt < 64; ++jt) {
        const int j0 = jt * 64;
#pragma unroll
        for (int r = 0; r < 8; ++r) {
            int idx = tid + r * 256;
            int d = idx >> 6, j = idx & 63;
            float kv = Kp[(size_t)d * NTOK + j0 + j];
            float vv = Vp[(size_t)d * NTOK + j0 + j];
            k_s[d][j] = kv;
            vT[j][d]  = vv;
        }
        __syncthreads();

        // S = q^T k  (K = 32)
        float S[4][4] = {};
#pragma unroll
        for (int d = 0; d < DHEAD; ++d) {
            float4 qa = *(float4*)&q_s[d][ty * 4];
            float4 kb = *(float4*)&k_s[d][tx * 4];
            float qv[4] = {qa.x, qa.y, qa.z, qa.w};
            float kv[4] = {kb.x, kb.y, kb.z, kb.w};
#pragma unroll
            for (int a = 0; a < 4; ++a)
#pragma unroll
                for (int c = 0; c < 4; ++c)
                    S[a][c] = fmaf(qv[a], kv[c], S[a][c]);
        }

        // online softmax update (row reduce across 16-lane groups)
#pragma unroll
        for (int a = 0; a < 4; ++a) {
            float rmax = fmaxf(fmaxf(S[a][0], S[a][1]),
                               fmaxf(S[a][2], S[a][3])) * scale;
#pragma unroll
            for (int off = 8; off; off >>= 1)
                rmax = fmaxf(rmax, __shfl_xor_sync(0xffffffffu, rmax, off));
            float m_new = fmaxf(m_i[a], rmax);
            float p[4], rs = 0.f;
#pragma unroll
            for (int c = 0; c < 4; ++c) {
                p[c] = __expf(fmaf(S[a][c], scale, -m_new));
                rs += p[c];
            }
#pragma unroll
            for (int off = 8; off; off >>= 1)
                rs += __shfl_xor_sync(0xffffffffu, rs, off);
            float corr = __expf(m_i[a] - m_new);
            l_i[a] = l_i[a] * corr + rs;
            m_i[a] = m_new;
            O[a][0] *= corr; O[a][1] *= corr;
            *(float4*)&P_s[ty * 4 + a][tx * 4] =
                make_float4(p[0], p[1], p[2], p[3]);
        }
        __syncthreads();

        // O += P @ V^T  (reduce over 64 keys)
#pragma unroll
        for (int jj = 0; jj < 64; jj += 4) {
            float2 v0 = *(float2*)&vT[jj + 0][d0];
            float2 v1 = *(float2*)&vT[jj + 1][d0];
            float2 v2 = *(float2*)&vT[jj + 2][d0];
            float2 v3 = *(float2*)&vT[jj + 3][d0];
#pragma unroll
            for (int a = 0; a < 4; ++a) {
                float4 p = *(float4*)&P_s[ty * 4 + a][jj];
                O[a][0] = fmaf(p.x, v0.x, fmaf(p.y, v1.x,
                          fmaf(p.z, v2.x, fmaf(p.w, v3.x, O[a][0]))));
                O[a][1] = fmaf(p.x, v0.y, fmaf(p.y, v1.y,
                          fmaf(p.z, v2.y, fmaf(p.w, v3.y, O[a][1]))));
            }
        }
        __syncthreads();
    }

    float* A = g_att + ((size_t)b * HID + h * DHEAD) * NTOK + q0;
#pragma unroll
    for (int a = 0; a < 4; ++a) {
        float inv = 1.0f / l_i[a];
        A[(size_t)(d0 + 0) * NTOK + ty * 4 + a] = O[a][0] * inv;
        A[(size_t)(d0 + 1) * NTOK + ty * 4 + a] = O[a][1] * inv;
    }
}

// ---------------------------------------------------------------------------
// Kernel 3: out = W_out (256x128) @ g_att[b] (128x4096) + b_out
// ---------------------------------------------------------------------------
__global__ __launch_bounds__(256) void proj_gemm(const float* __restrict__ Wo,
                                                 const float* __restrict__ bias,
                                                 float* __restrict__ Out) {
    __shared__ float Ws[16][64];
    __shared__ float Xs[16][64];

    const int b  = blockIdx.z;
    const int M0 = blockIdx.y * 64;
    const int N0 = blockIdx.x * 64;
    const int tid = threadIdx.x;
    const int tx = tid & 15, ty = tid >> 4;

    const float* Xb = g_att + (size_t)b * HID * NTOK;

    const int wm = tid >> 2,  wk = (tid & 3) * 4;
    const int xk = tid >> 4,  xn = (tid & 15) * 4;

    float acc[4][4] = {};

    for (int kk = 0; kk < HID; kk += 16) {
        float4 w4 = *(const float4*)&Wo[(size_t)(M0 + wm) * HID + kk + wk];
        Ws[wk + 0][wm] = w4.x; Ws[wk + 1][wm] = w4.y;
        Ws[wk + 2][wm] = w4.z; Ws[wk + 3][wm] = w4.w;
        *(float4*)&Xs[xk][xn] =
            *(const float4*)&Xb[(size_t)(kk + xk) * NTOK + N0 + xn];
        __syncthreads();
#pragma unroll
        for (int k = 0; k < 16; ++k) {
            float4 a4 = *(float4*)&Ws[k][ty * 4];
            float4 b4 = *(float4*)&Xs[k][tx * 4];
            float av[4] = {a4.x, a4.y, a4.z, a4.w};
            float bv[4] = {b4.x, b4.y, b4.z, b4.w};
#pragma unroll
            for (int a = 0; a < 4; ++a)
#pragma unroll
                for (int c = 0; c < 4; ++c)
                    acc[a][c] = fmaf(av[a], bv[c], acc[a][c]);
        }
        __syncthreads();
    }

    float* Cb = Out + (size_t)b * CIN * NTOK;
#pragma unroll
    for (int a = 0; a < 4; ++a) {
        float bv = bias[M0 + ty * 4 + a];
        float4 o = make_float4(acc[a][0] + bv, acc[a][1] + bv,
                               acc[a][2] + bv, acc[a][3] + bv);
        *(float4*)&Cb[(size_t)(M0 + ty * 4 + a) * NTOK + N0 + tx * 4] = o;
    }
}

// ---------------------------------------------------------------------------
extern "C" void kernel_launch(void* const* d_in, const int* in_sizes, int n_in,
                              void* d_out, int out_size) {
    const float* x     = (const float*)d_in[0];  // (4,256,64,64)
    const float* w_qkv = (const float*)d_in[1];  // (384,256)
    const float* w_out = (const float*)d_in[2];  // (256,128)
    const float* b_out = (const float*)d_in[3];  // (256,)
    float* out = (float*)d_out;                  // (4,256,64,64)

    qkv_gemm<<<dim3(64, 6, BATCH), 256>>>(x, w_qkv);
    attn_kernel<<<dim3(64, 16), 256>>>();
    proj_gemm<<<dim3(64, 4, BATCH), 256>>>(w_out, b_out, out);
}

// round 4
// speedup vs baseline: 2.5061x; 2.5061x over previous
#include <cuda_runtime.h>
#include <cuda_bf16.h>

#define BATCH   4
#define CIN     256
#define HID     128
#define NHEADS  4
#define DHEAD   32
#define NTOK    4096
#define QKV_ROWS 384

#define BQ 128   // queries per block
#define BK 64    // keys per tile

// Scratch (no allocations allowed in kernel_launch)
__device__ float g_qkv[BATCH * QKV_ROWS * NTOK];   // [b][384][4096]
__device__ float g_att[BATCH * HID * NTOK];        // [b][128][4096]

// ---------------------------------------------------------------------------
// Kernel 1: qkv = W_qkv (384x256) @ x[b] (256x4096)   -> g_qkv
// ---------------------------------------------------------------------------
__global__ __launch_bounds__(256) void qkv_gemm(const float* __restrict__ X,
                                                const float* __restrict__ W) {
    __shared__ float Ws[16][64];
    __shared__ float Xs[16][64];

    const int b  = blockIdx.z;
    const int M0 = blockIdx.y * 64;
    const int N0 = blockIdx.x * 64;
    const int tid = threadIdx.x;
    const int tx = tid & 15, ty = tid >> 4;

    const float* Xb = X + (size_t)b * CIN * NTOK;

    const int wm = tid >> 2,  wk = (tid & 3) * 4;
    const int xk = tid >> 4,  xn = (tid & 15) * 4;

    float acc[4][4] = {};

    for (int kk = 0; kk < CIN; kk += 16) {
        float4 w4 = *(const float4*)&W[(size_t)(M0 + wm) * CIN + kk + wk];
        Ws[wk + 0][wm] = w4.x; Ws[wk + 1][wm] = w4.y;
        Ws[wk + 2][wm] = w4.z; Ws[wk + 3][wm] = w4.w;
        *(float4*)&Xs[xk][xn] =
            *(const float4*)&Xb[(size_t)(kk + xk) * NTOK + N0 + xn];
        __syncthreads();
#pragma unroll
        for (int k = 0; k < 16; ++k) {
            float4 a4 = *(float4*)&Ws[k][ty * 4];
            float4 b4 = *(float4*)&Xs[k][tx * 4];
            float av[4] = {a4.x, a4.y, a4.z, a4.w};
            float bv[4] = {b4.x, b4.y, b4.z, b4.w};
#pragma unroll
            for (int a = 0; a < 4; ++a)
#pragma unroll
                for (int c = 0; c < 4; ++c)
                    acc[a][c] = fmaf(av[a], bv[c], acc[a][c]);
        }
        __syncthreads();
    }

    float* Cb = g_qkv + (size_t)b * QKV_ROWS * NTOK;
#pragma unroll
    for (int a = 0; a < 4; ++a) {
        float4 o = make_float4(acc[a][0], acc[a][1], acc[a][2], acc[a][3]);
        *(float4*)&Cb[(size_t)(M0 + ty * 4 + a) * NTOK + N0 + tx * 4] = o;
    }
}

// ---------------------------------------------------------------------------
// Tensor-core flash attention (mma.sync m16n8k16 bf16, 3-term hi/lo split).
// Block = 128 queries x all keys; 8 warps; warp w owns rows [w*16, w*16+16).
// Per key tile (64): S = Q K^T on tensor pipe, online softmax in registers,
// P re-used directly as A-fragments (C-layout == A-layout), O += P V^T.
// ---------------------------------------------------------------------------
__device__ __forceinline__ void mma_bf16(float (&c)[4], const unsigned (&a)[4],
                                         unsigned b0, unsigned b1) {
    asm volatile(
        "mma.sync.aligned.m16n8k16.row.col.f32.bf16.bf16.f32 "
        "{%0,%1,%2,%3}, {%4,%5,%6,%7}, {%8,%9}, {%0,%1,%2,%3};"
        : "+f"(c[0]), "+f"(c[1]), "+f"(c[2]), "+f"(c[3])
        : "r"(a[0]), "r"(a[1]), "r"(a[2]), "r"(a[3]), "r"(b0), "r"(b1));
}

__device__ __forceinline__ void split2(float x, float y,
                                       unsigned& hi, unsigned& lo) {
    __nv_bfloat162 h = __floats2bfloat162_rn(x, y);
    float hx = __bfloat162float(h.x);
    float hy = __bfloat162float(h.y);
    __nv_bfloat162 l = __floats2bfloat162_rn(x - hx, y - hy);
    hi = *reinterpret_cast<unsigned*>(&h);
    lo = *reinterpret_cast<unsigned*>(&l);
}

__device__ __forceinline__ float fast_exp2(float x) {
    float y;
    asm("ex2.approx.ftz.f32 %0, %1;" : "=f"(y) : "f"(x));
    return y;
}

__global__ __launch_bounds__(256, 2) void attn_mma() {
    // K tile: pairs along d: khi[d/2][j], word stride 72 (conflict-free frags)
    __shared__ unsigned khi[16][72];
    __shared__ unsigned klo[16][72];
    // V tile: pairs along j: vhi[d][j/2], word stride 36
    __shared__ unsigned vhi[32][36];
    __shared__ unsigned vlo[32][36];

    const int bh = blockIdx.y;
    const int b = bh >> 2, h = bh & 3;
    const int q0 = blockIdx.x * BQ;
    const int tid = threadIdx.x;
    const int w = tid >> 5;
    const int t = tid & 31;
    const int tg = t >> 2;   // fragment row group
    const int tq = t & 3;    // fragment quad

    const float* Qp = g_qkv + ((size_t)b * QKV_ROWS + h * DHEAD) * NTOK;
    const float* Kp = g_qkv + ((size_t)b * QKV_ROWS + HID + h * DHEAD) * NTOK;
    const float* Vp = g_qkv + ((size_t)b * QKV_ROWS + 2 * HID + h * DHEAD) * NTOK;

    const int gia = q0 + w * 16 + tg;   // global query row (fragment rows 0-7)
    const int gib = gia + 8;            // fragment rows 8-15

    // Q fragments, scale * log2(e) folded in (softmax done in base 2).
    const float qscale = 0.17677669529663689f * 1.4426950408889634f;
    unsigned Qh[2][4], Ql[2][4];
#pragma unroll
    for (int kt = 0; kt < 2; ++kt) {
#pragma unroll
        for (int hh = 0; hh < 2; ++hh) {
            int d0 = kt * 16 + tq * 2 + hh * 8;
            float xa0 = Qp[(size_t)d0 * NTOK + gia] * qscale;
            float xa1 = Qp[(size_t)(d0 + 1) * NTOK + gia] * qscale;
            float xb0 = Qp[(size_t)d0 * NTOK + gib] * qscale;
            float xb1 = Qp[(size_t)(d0 + 1) * NTOK + gib] * qscale;
            split2(xa0, xa1, Qh[kt][hh * 2 + 0], Ql[kt][hh * 2 + 0]);
            split2(xb0, xb1, Qh[kt][hh * 2 + 1], Ql[kt][hh * 2 + 1]);
        }
    }

    float m_a = -1e30f, m_b = -1e30f, l_a = 0.f, l_b = 0.f;
    float O[4][4] = {};
    float S[8][4];

    for (int jt = 0; jt < NTOK / BK; ++jt) {
        const int j0 = jt * BK;

        // ---- load + bf16-split K and V tiles into smem ----
#pragma unroll
        for (int r = 0; r < 4; ++r) {
            int i2 = tid + r * 256;              // 0..1023
            // K: pair along d
            int kp = i2 >> 6, j = i2 & 63;
            float x0 = Kp[(size_t)(2 * kp) * NTOK + j0 + j];
            float x1 = Kp[(size_t)(2 * kp + 1) * NTOK + j0 + j];
            split2(x0, x1, khi[kp][j], klo[kp][j]);
            // V: pair along j
            int d = i2 >> 5, jp = i2 & 31;
            float2 v2 = *(const float2*)&Vp[(size_t)d * NTOK + j0 + 2 * jp];
            split2(v2.x, v2.y, vhi[d][jp], vlo[d][jp]);
        }
        __syncthreads();

        // ---- S = (Q*scale*log2e) K^T  (16 x 64 per warp) ----
#pragma unroll
        for (int nt = 0; nt < 8; ++nt) {
            S[nt][0] = 0.f; S[nt][1] = 0.f; S[nt][2] = 0.f; S[nt][3] = 0.f;
#pragma unroll
            for (int kt = 0; kt < 2; ++kt) {
                int row = kt * 8 + tq;
                int col = nt * 8 + tg;
                unsigned bh0 = khi[row][col], bh1 = khi[row + 4][col];
                unsigned bl0 = klo[row][col], bl1 = klo[row + 4][col];
                mma_bf16(S[nt], Qh[kt], bh0, bh1);
                mma_bf16(S[nt], Qh[kt], bl0, bl1);
                mma_bf16(S[nt], Ql[kt], bh0, bh1);
            }
        }

        // ---- online softmax (base-2), rows fully warp-local ----
        float mxa = S[0][0], mxb = S[0][2];
#pragma unroll
        for (int nt = 0; nt < 8; ++nt) {
            mxa = fmaxf(mxa, fmaxf(S[nt][0], S[nt][1]));
            mxb = fmaxf(mxb, fmaxf(S[nt][2], S[nt][3]));
        }
        mxa = fmaxf(mxa, __shfl_xor_sync(0xffffffffu, mxa, 1));
        mxa = fmaxf(mxa, __shfl_xor_sync(0xffffffffu, mxa, 2));
        mxb = fmaxf(mxb, __shfl_xor_sync(0xffffffffu, mxb, 1));
        mxb = fmaxf(mxb, __shfl_xor_sync(0xffffffffu, mxb, 2));

        float mna = fmaxf(m_a, mxa), mnb = fmaxf(m_b, mxb);
        float ca = fast_exp2(m_a - mna), cb = fast_exp2(m_b - mnb);

        float rsa = 0.f, rsb = 0.f;
#pragma unroll
        for (int nt = 0; nt < 8; ++nt) {
            S[nt][0] = fast_exp2(S[nt][0] - mna);
            S[nt][1] = fast_exp2(S[nt][1] - mna);
            S[nt][2] = fast_exp2(S[nt][2] - mnb);
            S[nt][3] = fast_exp2(S[nt][3] - mnb);
            rsa += S[nt][0] + S[nt][1];
            rsb += S[nt][2] + S[nt][3];
        }
        rsa += __shfl_xor_sync(0xffffffffu, rsa, 1);
        rsa += __shfl_xor_sync(0xffffffffu, rsa, 2);
        rsb += __shfl_xor_sync(0xffffffffu, rsb, 1);
        rsb += __shfl_xor_sync(0xffffffffu, rsb, 2);

        l_a = l_a * ca + rsa;  m_a = mna;
        l_b = l_b * cb + rsb;  m_b = mnb;

#pragma unroll
        for (int dn = 0; dn < 4; ++dn) {
            O[dn][0] *= ca; O[dn][1] *= ca;
            O[dn][2] *= cb; O[dn][3] *= cb;
        }

        // ---- O += P V^T : P fragments straight from S registers ----
#pragma unroll
        for (int pk = 0; pk < 4; ++pk) {
            unsigned Ph[4], Pl[4];
            split2(S[2 * pk][0],     S[2 * pk][1],     Ph[0], Pl[0]);
            split2(S[2 * pk][2],     S[2 * pk][3],     Ph[1], Pl[1]);
            split2(S[2 * pk + 1][0], S[2 * pk + 1][1], Ph[2], Pl[2]);
            split2(S[2 * pk + 1][2], S[2 * pk + 1][3], Ph[3], Pl[3]);
#pragma unroll
            for (int dn = 0; dn < 4; ++dn) {
                int vr = dn * 8 + tg;
                int vc = pk * 8 + tq;
                unsigned vh0 = vhi[vr][vc], vh1 = vhi[vr][vc + 4];
                unsigned vl0 = vlo[vr][vc], vl1 = vlo[vr][vc + 4];
                mma_bf16(O[dn], Ph, vh0, vh1);
                mma_bf16(O[dn], Ph, vl0, vl1);
                mma_bf16(O[dn], Pl, vh0, vh1);
            }
        }
        __syncthreads();
    }

    // ---- normalize + write O (d-major, matches proj_gemm input) ----
    const float ila = 1.0f / l_a, ilb = 1.0f / l_b;
    float* A = g_att + ((size_t)b * HID + h * DHEAD) * NTOK;
#pragma unroll
    for (int dn = 0; dn < 4; ++dn) {
        int d = dn * 8 + tq * 2;
        A[(size_t)d * NTOK + gia]       = O[dn][0] * ila;
        A[(size_t)(d + 1) * NTOK + gia] = O[dn][1] * ila;
        A[(size_t)d * NTOK + gib]       = O[dn][2] * ilb;
        A[(size_t)(d + 1) * NTOK + gib] = O[dn][3] * ilb;
    }
}

// ---------------------------------------------------------------------------
// Kernel 3: out = W_out (256x128) @ g_att[b] (128x4096) + b_out
// ---------------------------------------------------------------------------
__global__ __launch_bounds__(256) void proj_gemm(const float* __restrict__ Wo,
                                                 const float* __restrict__ bias,
                                                 float* __restrict__ Out) {
    __shared__ float Ws[16][64];
    __shared__ float Xs[16][64];

    const int b  = blockIdx.z;
    const int M0 = blockIdx.y * 64;
    const int N0 = blockIdx.x * 64;
    const int tid = threadIdx.x;
    const int tx = tid & 15, ty = tid >> 4;

    const float* Xb = g_att + (size_t)b * HID * NTOK;

    const int wm = tid >> 2,  wk = (tid & 3) * 4;
    const int xk = tid >> 4,  xn = (tid & 15) * 4;

    float acc[4][4] = {};

    for (int kk = 0; kk < HID; kk += 16) {
        float4 w4 = *(const float4*)&Wo[(size_t)(M0 + wm) * HID + kk + wk];
        Ws[wk + 0][wm] = w4.x; Ws[wk + 1][wm] = w4.y;
        Ws[wk + 2][wm] = w4.z; Ws[wk + 3][wm] = w4.w;
        *(float4*)&Xs[xk][xn] =
            *(const float4*)&Xb[(size_t)(kk + xk) * NTOK + N0 + xn];
        __syncthreads();
#pragma unroll
        for (int k = 0; k < 16; ++k) {
            float4 a4 = *(float4*)&Ws[k][ty * 4];
            float4 b4 = *(float4*)&Xs[k][tx * 4];
            float av[4] = {a4.x, a4.y, a4.z, a4.w};
            float bv[4] = {b4.x, b4.y, b4.z, b4.w};
#pragma unroll
            for (int a = 0; a < 4; ++a)
#pragma unroll
                for (int c = 0; c < 4; ++c)
                    acc[a][c] = fmaf(av[a], bv[c], acc[a][c]);
        }
        __syncthreads();
    }

    float* Cb = Out + (size_t)b * CIN * NTOK;
#pragma unroll
    for (int a = 0; a < 4; ++a) {
        float bv = bias[M0 + ty * 4 + a];
        float4 o = make_float4(acc[a][0] + bv, acc[a][1] + bv,
                               acc[a][2] + bv, acc[a][3] + bv);
        *(float4*)&Cb[(size_t)(M0 + ty * 4 + a) * NTOK + N0 + tx * 4] = o;
    }
}

// ---------------------------------------------------------------------------
extern "C" void kernel_launch(void* const* d_in, const int* in_sizes, int n_in,
                              void* d_out, int out_size) {
    const float* x     = (const float*)d_in[0];  // (4,256,64,64)
    const float* w_qkv = (const float*)d_in[1];  // (384,256)
    const float* w_out = (const float*)d_in[2];  // (256,128)
    const float* b_out = (const float*)d_in[3];  // (256,)
    float* out = (float*)d_out;                  // (4,256,64,64)

    qkv_gemm<<<dim3(64, 6, BATCH), 256>>>(x, w_qkv);
    attn_mma<<<dim3(NTOK / BQ, 16), 256>>>();
    proj_gemm<<<dim3(64, 4, BATCH), 256>>>(w_out, b_out, out);
}

// round 5
// speedup vs baseline: 2.7934x; 1.1146x over previous
#include <cuda_runtime.h>
#include <cuda_bf16.h>

#define BATCH   4
#define CIN     256
#define HID     128
#define NHEADS  4
#define DHEAD   32
#define NTOK    4096
#define QKV_ROWS 384

#define BQ 128   // queries per block (attention)
#define BK 64    // keys per tile (attention)

// ---------------- scratch (__device__ globals; no allocs allowed) ----------
__device__ float    g_qkv[BATCH * QKV_ROWS * NTOK];          // f32 qkv
__device__ unsigned g_xh[BATCH * 128 * NTOK];                // x split, c-pairs
__device__ unsigned g_xl[BATCH * 128 * NTOK];
__device__ unsigned g_wqh[128 * 384];                        // W_qkv^T split [kp][m]
__device__ unsigned g_wql[128 * 384];
__device__ unsigned g_woh[64 * 256];                         // W_out^T split [kp][m]
__device__ unsigned g_wol[64 * 256];
__device__ unsigned g_kh[BATCH * NHEADS * 16 * NTOK];        // K split, d-pairs
__device__ unsigned g_kl[BATCH * NHEADS * 16 * NTOK];
__device__ unsigned g_vh[BATCH * NHEADS * 32 * (NTOK / 2)];  // V split, n-pairs
__device__ unsigned g_vl[BATCH * NHEADS * 32 * (NTOK / 2)];
__device__ unsigned g_ah[BATCH * 64 * NTOK];                 // attn out split, d-pairs
__device__ unsigned g_al[BATCH * 64 * NTOK];

// ---------------- helpers --------------------------------------------------
__device__ __forceinline__ void mma_bf16(float (&c)[4], const unsigned (&a)[4],
                                         unsigned b0, unsigned b1) {
    asm volatile(
        "mma.sync.aligned.m16n8k16.row.col.f32.bf16.bf16.f32 "
        "{%0,%1,%2,%3}, {%4,%5,%6,%7}, {%8,%9}, {%0,%1,%2,%3};"
        : "+f"(c[0]), "+f"(c[1]), "+f"(c[2]), "+f"(c[3])
        : "r"(a[0]), "r"(a[1]), "r"(a[2]), "r"(a[3]), "r"(b0), "r"(b1));
}

__device__ __forceinline__ void split2(float x, float y,
                                       unsigned& hi, unsigned& lo) {
    __nv_bfloat162 h = __floats2bfloat162_rn(x, y);
    float hx = __bfloat162float(h.x);
    float hy = __bfloat162float(h.y);
    __nv_bfloat162 l = __floats2bfloat162_rn(x - hx, y - hy);
    hi = *reinterpret_cast<unsigned*>(&h);
    lo = *reinterpret_cast<unsigned*>(&l);
}

__device__ __forceinline__ float fast_exp2(float x) {
    float y;
    asm("ex2.approx.ftz.f32 %0, %1;" : "=f"(y) : "f"(x));
    return y;
}

// ---------------- repack kernels ------------------------------------------
// x (b,256,4096) f32 -> c-pair packed bf16 hi/lo  [b][cp 128][n 4096]
__global__ __launch_bounds__(256) void split_x(const float* __restrict__ x) {
    int i = blockIdx.x * 256 + threadIdx.x;          // 0 .. 2M-1
    int n  = i & 4095;
    int cp = (i >> 12) & 127;
    int b  = i >> 19;
    const float* p = x + ((size_t)b * 256 + 2 * cp) * 4096 + n;
    unsigned hi, lo;
    split2(p[0], p[4096], hi, lo);
    g_xh[i] = hi; g_xl[i] = lo;
}

// weights -> transposed k-pair packed splits
__global__ __launch_bounds__(256) void split_w(const float* __restrict__ wq,
                                               const float* __restrict__ wo) {
    int i = blockIdx.x * 256 + threadIdx.x;          // 0 .. 65535
    if (i < 128 * 384) {
        int kp = i / 384, m = i - kp * 384;
        unsigned hi, lo;
        split2(wq[m * 256 + 2 * kp], wq[m * 256 + 2 * kp + 1], hi, lo);
        g_wqh[i] = hi; g_wql[i] = lo;
    } else {
        int j = i - 128 * 384;                       // 0 .. 16383
        int kp = j / 256, m = j - kp * 256;
        unsigned hi, lo;
        split2(wo[m * 128 + 2 * kp], wo[m * 128 + 2 * kp + 1], hi, lo);
        g_woh[j] = hi; g_wol[j] = lo;
    }
}

// K (d-pairs) and V (n-pairs) sections of g_qkv -> packed bf16 hi/lo
__global__ __launch_bounds__(256) void split_kv() {
    int i = blockIdx.x * 256 + threadIdx.x;          // 0 .. 2M-1
    const int KTOT = BATCH * NHEADS * 16 * NTOK;     // 1,048,576
    if (i < KTOT) {
        int n  = i & 4095;
        int dp = (i >> 12) & 15;
        int bh = i >> 16;
        int b = bh >> 2, h = bh & 3;
        const float* row =
            g_qkv + ((size_t)(b * 384 + 128 + h * 32 + 2 * dp)) * 4096;
        unsigned hi, lo;
        split2(row[n], row[4096 + n], hi, lo);
        g_kh[i] = hi; g_kl[i] = lo;
    } else {
        int j = i - KTOT;                            // 0 .. 1M-1
        int np = j & 2047;
        int d  = (j >> 11) & 31;
        int bh = j >> 16;
        int b = bh >> 2, h = bh & 3;
        float2 v = *(const float2*)(g_qkv +
                     ((size_t)(b * 384 + 256 + h * 32 + d)) * 4096 + 2 * np);
        unsigned hi, lo;
        split2(v.x, v.y, hi, lo);
        g_vh[j] = hi; g_vl[j] = lo;
    }
}

// ---------------- Kernel 1: qkv GEMM on tensor pipe ------------------------
// C[b] (384x4096) = W_qkv (384x256) @ X[b] (256x4096), bf16 3-term.
// Block 128x128, 8 warps (4M x 2N), warp tile 32x64.
__global__ __launch_bounds__(256) void qkv_mma() {
    __shared__ unsigned Ah[8][136], Al[8][136];
    __shared__ unsigned Bh[8][136], Bl[8][136];

    const int b  = blockIdx.z;
    const int M0 = blockIdx.y * 128;
    const int N0 = blockIdx.x * 128;
    const int tid = threadIdx.x;
    const int w = tid >> 5, t = tid & 31;
    const int tg = t >> 2, tq = t & 3;
    const int wmi = w >> 1, wni = w & 1;

    float C[2][8][4] = {};

    for (int s = 0; s < 16; ++s) {
        const int kp0 = s * 8;
#pragma unroll
        for (int r = 0; r < 4; ++r) {
            int i2 = tid + r * 256;
            int kp = i2 >> 7, m = i2 & 127;
            Ah[kp][m] = g_wqh[(kp0 + kp) * 384 + M0 + m];
            Al[kp][m] = g_wql[(kp0 + kp) * 384 + M0 + m];
            size_t xb = ((size_t)b * 128 + kp0 + kp) * 4096 + N0 + m;
            Bh[kp][m] = g_xh[xb];
            Bl[kp][m] = g_xl[xb];
        }
        __syncthreads();

        unsigned ah[2][4], al[2][4];
#pragma unroll
        for (int mt = 0; mt < 2; ++mt) {
            int r0 = wmi * 32 + mt * 16;
            ah[mt][0] = Ah[tq][r0 + tg];     ah[mt][1] = Ah[tq][r0 + tg + 8];
            ah[mt][2] = Ah[tq + 4][r0 + tg]; ah[mt][3] = Ah[tq + 4][r0 + tg + 8];
            al[mt][0] = Al[tq][r0 + tg];     al[mt][1] = Al[tq][r0 + tg + 8];
            al[mt][2] = Al[tq + 4][r0 + tg]; al[mt][3] = Al[tq + 4][r0 + tg + 8];
        }
#pragma unroll
        for (int nt = 0; nt < 8; ++nt) {
            int c0 = wni * 64 + nt * 8 + tg;
            unsigned bh0 = Bh[tq][c0], bh1 = Bh[tq + 4][c0];
            unsigned bl0 = Bl[tq][c0], bl1 = Bl[tq + 4][c0];
#pragma unroll
            for (int mt = 0; mt < 2; ++mt) {
                mma_bf16(C[mt][nt], ah[mt], bh0, bh1);
                mma_bf16(C[mt][nt], ah[mt], bl0, bl1);
                mma_bf16(C[mt][nt], al[mt], bh0, bh1);
            }
        }
        __syncthreads();
    }

    float* Cb = g_qkv + ((size_t)b * QKV_ROWS + M0) * NTOK + N0;
#pragma unroll
    for (int mt = 0; mt < 2; ++mt) {
#pragma unroll
        for (int nt = 0; nt < 8; ++nt) {
            int r0 = wmi * 32 + mt * 16 + tg;
            int c0 = wni * 64 + nt * 8 + tq * 2;
            *(float2*)&Cb[(size_t)r0 * NTOK + c0] =
                make_float2(C[mt][nt][0], C[mt][nt][1]);
            *(float2*)&Cb[(size_t)(r0 + 8) * NTOK + c0] =
                make_float2(C[mt][nt][2], C[mt][nt][3]);
        }
    }
}

// ---------------- Kernel 2: tensor-core flash attention --------------------
__global__ __launch_bounds__(256, 2) void attn_mma() {
    __shared__ unsigned khi[16][72];
    __shared__ unsigned klo[16][72];
    __shared__ unsigned vhi[32][36];
    __shared__ unsigned vlo[32][36];

    const int bh = blockIdx.y;
    const int b = bh >> 2, h = bh & 3;
    const int q0 = blockIdx.x * BQ;
    const int tid = threadIdx.x;
    const int w = tid >> 5;
    const int t = tid & 31;
    const int tg = t >> 2;
    const int tq = t & 3;

    const float* Qp = g_qkv + ((size_t)b * QKV_ROWS + h * DHEAD) * NTOK;

    const int gia = q0 + w * 16 + tg;
    const int gib = gia + 8;

    const float qscale = 0.17677669529663689f * 1.4426950408889634f;
    unsigned Qh[2][4], Ql[2][4];
#pragma unroll
    for (int kt = 0; kt < 2; ++kt) {
#pragma unroll
        for (int hh = 0; hh < 2; ++hh) {
            int d0 = kt * 16 + tq * 2 + hh * 8;
            float xa0 = Qp[(size_t)d0 * NTOK + gia] * qscale;
            float xa1 = Qp[(size_t)(d0 + 1) * NTOK + gia] * qscale;
            float xb0 = Qp[(size_t)d0 * NTOK + gib] * qscale;
            float xb1 = Qp[(size_t)(d0 + 1) * NTOK + gib] * qscale;
            split2(xa0, xa1, Qh[kt][hh * 2 + 0], Ql[kt][hh * 2 + 0]);
            split2(xb0, xb1, Qh[kt][hh * 2 + 1], Ql[kt][hh * 2 + 1]);
        }
    }

    float m_a = -1e30f, m_b = -1e30f, l_a = 0.f, l_b = 0.f;
    float O[4][4] = {};
    float S[8][4];

    for (int jt = 0; jt < NTOK / BK; ++jt) {
        const int j0 = jt * BK;

        // ---- load pre-split K/V tiles ----
#pragma unroll
        for (int r = 0; r < 4; ++r) {
            int i2 = tid + r * 256;
            int kp = i2 >> 6, j = i2 & 63;
            size_t kb = ((size_t)bh * 16 + kp) * 4096 + j0 + j;
            khi[kp][j] = g_kh[kb];
            klo[kp][j] = g_kl[kb];
            int d = i2 >> 5, jp = i2 & 31;
            size_t vb = ((size_t)bh * 32 + d) * 2048 + (j0 >> 1) + jp;
            vhi[d][jp] = g_vh[vb];
            vlo[d][jp] = g_vl[vb];
        }
        __syncthreads();

        // ---- S = (Q*scale*log2e) K^T ----
#pragma unroll
        for (int nt = 0; nt < 8; ++nt) {
            S[nt][0] = 0.f; S[nt][1] = 0.f; S[nt][2] = 0.f; S[nt][3] = 0.f;
#pragma unroll
            for (int kt = 0; kt < 2; ++kt) {
                int row = kt * 8 + tq;
                int col = nt * 8 + tg;
                unsigned bh0 = khi[row][col], bh1 = khi[row + 4][col];
                unsigned bl0 = klo[row][col], bl1 = klo[row + 4][col];
                mma_bf16(S[nt], Qh[kt], bh0, bh1);
                mma_bf16(S[nt], Qh[kt], bl0, bl1);
                mma_bf16(S[nt], Ql[kt], bh0, bh1);
            }
        }

        // ---- online softmax (base-2) ----
        float mxa = S[0][0], mxb = S[0][2];
#pragma unroll
        for (int nt = 0; nt < 8; ++nt) {
            mxa = fmaxf(mxa, fmaxf(S[nt][0], S[nt][1]));
            mxb = fmaxf(mxb, fmaxf(S[nt][2], S[nt][3]));
        }
        mxa = fmaxf(mxa, __shfl_xor_sync(0xffffffffu, mxa, 1));
        mxa = fmaxf(mxa, __shfl_xor_sync(0xffffffffu, mxa, 2));
        mxb = fmaxf(mxb, __shfl_xor_sync(0xffffffffu, mxb, 1));
        mxb = fmaxf(mxb, __shfl_xor_sync(0xffffffffu, mxb, 2));

        float mna = fmaxf(m_a, mxa), mnb = fmaxf(m_b, mxb);
        float ca = fast_exp2(m_a - mna), cb = fast_exp2(m_b - mnb);

        float rsa = 0.f, rsb = 0.f;
#pragma unroll
        for (int nt = 0; nt < 8; ++nt) {
            S[nt][0] = fast_exp2(S[nt][0] - mna);
            S[nt][1] = fast_exp2(S[nt][1] - mna);
            S[nt][2] = fast_exp2(S[nt][2] - mnb);
            S[nt][3] = fast_exp2(S[nt][3] - mnb);
            rsa += S[nt][0] + S[nt][1];
            rsb += S[nt][2] + S[nt][3];
        }
        rsa += __shfl_xor_sync(0xffffffffu, rsa, 1);
        rsa += __shfl_xor_sync(0xffffffffu, rsa, 2);
        rsb += __shfl_xor_sync(0xffffffffu, rsb, 1);
        rsb += __shfl_xor_sync(0xffffffffu, rsb, 2);

        l_a = l_a * ca + rsa;  m_a = mna;
        l_b = l_b * cb + rsb;  m_b = mnb;

#pragma unroll
        for (int dn = 0; dn < 4; ++dn) {
            O[dn][0] *= ca; O[dn][1] *= ca;
            O[dn][2] *= cb; O[dn][3] *= cb;
        }

        // ---- O += P V^T ----
#pragma unroll
        for (int pk = 0; pk < 4; ++pk) {
            unsigned Ph[4], Pl[4];
            split2(S[2 * pk][0],     S[2 * pk][1],     Ph[0], Pl[0]);
            split2(S[2 * pk][2],     S[2 * pk][3],     Ph[1], Pl[1]);
            split2(S[2 * pk + 1][0], S[2 * pk + 1][1], Ph[2], Pl[2]);
            split2(S[2 * pk + 1][2], S[2 * pk + 1][3], Ph[3], Pl[3]);
#pragma unroll
            for (int dn = 0; dn < 4; ++dn) {
                int vr = dn * 8 + tg;
                int vc = pk * 8 + tq;
                unsigned vh0 = vhi[vr][vc], vh1 = vhi[vr][vc + 4];
                unsigned vl0 = vlo[vr][vc], vl1 = vlo[vr][vc + 4];
                mma_bf16(O[dn], Ph, vh0, vh1);
                mma_bf16(O[dn], Ph, vl0, vl1);
                mma_bf16(O[dn], Pl, vh0, vh1);
            }
        }
        __syncthreads();
    }

    // ---- epilogue: normalize + write split d-pairs for proj ----
    const float ila = 1.0f / l_a, ilb = 1.0f / l_b;
#pragma unroll
    for (int dn = 0; dn < 4; ++dn) {
        size_t base = ((size_t)b * 64 + h * 16 + dn * 4 + tq) * 4096;
        unsigned hi, lo;
        split2(O[dn][0] * ila, O[dn][1] * ila, hi, lo);
        g_ah[base + gia] = hi; g_al[base + gia] = lo;
        split2(O[dn][2] * ilb, O[dn][3] * ilb, hi, lo);
        g_ah[base + gib] = hi; g_al[base + gib] = lo;
    }
}

// ---------------- Kernel 3: out projection on tensor pipe ------------------
// out[b] (256x4096) = W_out (256x128) @ att[b] (128x4096) + bias
__global__ __launch_bounds__(256) void proj_mma(const float* __restrict__ bias,
                                                float* __restrict__ Out) {
    __shared__ unsigned Ah[8][136], Al[8][136];
    __shared__ unsigned Bh[8][136], Bl[8][136];

    const int b  = blockIdx.z;
    const int M0 = blockIdx.y * 128;
    const int N0 = blockIdx.x * 128;
    const int tid = threadIdx.x;
    const int w = tid >> 5, t = tid & 31;
    const int tg = t >> 2, tq = t & 3;
    const int wmi = w >> 1, wni = w & 1;

    float C[2][8][4] = {};

    for (int s = 0; s < 8; ++s) {
        const int kp0 = s * 8;
#pragma unroll
        for (int r = 0; r < 4; ++r) {
            int i2 = tid + r * 256;
            int kp = i2 >> 7, m = i2 & 127;
            Ah[kp][m] = g_woh[(kp0 + kp) * 256 + M0 + m];
            Al[kp][m] = g_wol[(kp0 + kp) * 256 + M0 + m];
            size_t ab = ((size_t)b * 64 + kp0 + kp) * 4096 + N0 + m;
            Bh[kp][m] = g_ah[ab];
            Bl[kp][m] = g_al[ab];
        }
        __syncthreads();

        unsigned ah[2][4], al[2][4];
#pragma unroll
        for (int mt = 0; mt < 2; ++mt) {
            int r0 = wmi * 32 + mt * 16;
            ah[mt][0] = Ah[tq][r0 + tg];     ah[mt][1] = Ah[tq][r0 + tg + 8];
            ah[mt][2] = Ah[tq + 4][r0 + tg]; ah[mt][3] = Ah[tq + 4][r0 + tg + 8];
            al[mt][0] = Al[tq][r0 + tg];     al[mt][1] = Al[tq][r0 + tg + 8];
            al[mt][2] = Al[tq + 4][r0 + tg]; al[mt][3] = Al[tq + 4][r0 + tg + 8];
        }
#pragma unroll
        for (int nt = 0; nt < 8; ++nt) {
            int c0 = wni * 64 + nt * 8 + tg;
            unsigned bh0 = Bh[tq][c0], bh1 = Bh[tq + 4][c0];
            unsigned bl0 = Bl[tq][c0], bl1 = Bl[tq + 4][c0];
#pragma unroll
            for (int mt = 0; mt < 2; ++mt) {
                mma_bf16(C[mt][nt], ah[mt], bh0, bh1);
                mma_bf16(C[mt][nt], ah[mt], bl0, bl1);
                mma_bf16(C[mt][nt], al[mt], bh0, bh1);
            }
        }
        __syncthreads();
    }

    float* Cb = Out + ((size_t)b * CIN + M0) * NTOK + N0;
#pragma unroll
    for (int mt = 0; mt < 2; ++mt) {
        int r0 = wmi * 32 + mt * 16 + tg;
        float bv0 = bias[M0 + r0];
        float bv1 = bias[M0 + r0 + 8];
#pragma unroll
        for (int nt = 0; nt < 8; ++nt) {
            int c0 = wni * 64 + nt * 8 + tq * 2;
            *(float2*)&Cb[(size_t)r0 * NTOK + c0] =
                make_float2(C[mt][nt][0] + bv0, C[mt][nt][1] + bv0);
            *(float2*)&Cb[(size_t)(r0 + 8) * NTOK + c0] =
                make_float2(C[mt][nt][2] + bv1, C[mt][nt][3] + bv1);
        }
    }
}

// ---------------------------------------------------------------------------
extern "C" void kernel_launch(void* const* d_in, const int* in_sizes, int n_in,
                              void* d_out, int out_size) {
    const float* x     = (const float*)d_in[0];  // (4,256,64,64)
    const float* w_qkv = (const float*)d_in[1];  // (384,256)
    const float* w_out = (const float*)d_in[2];  // (256,128)
    const float* b_out = (const float*)d_in[3];  // (256,)
    float* out = (float*)d_out;                  // (4,256,64,64)

    split_x<<<8192, 256>>>(x);
    split_w<<<256, 256>>>(w_qkv, w_out);
    qkv_mma<<<dim3(32, 3, BATCH), 256>>>();
    split_kv<<<8192, 256>>>();
    attn_mma<<<dim3(NTOK / BQ, 16), 256>>>();
    proj_mma<<<dim3(32, 2, BATCH), 256>>>(b_out, out);
}